// round 1
// baseline (speedup 1.0000x reference)
#include <cuda_runtime.h>
#include <math.h>

// ---------------- scratch (static device arrays; no allocations) ----------------
__device__ float  g_h1[32 * 256 * 256];      // conv1 output (8 MB)
__device__ float  g_h2[64 * 128 * 128];      // conv2 output (4 MB)
__device__ float  g_feat[64];
__device__ float  g_f[256];
__device__ float  g_A[2 * 512 * 128 * 2];    // pre-GS u then v, complex interleaved
__device__ float2 g_G[2 * 128 * 128];        // Gram matrices
__device__ float2 g_RT[2 * 128 * 128];       // RT[j][k] = R[k][j] (k<j), RT[j][j] = 1/r_jj

// ---------------- conv1: (2,512,512) -> (32,256,256), 5x5 s2 p2, +bias, relu ----
__global__ void conv1_kernel(const float* __restrict__ x,
                             const float* __restrict__ w,
                             const float* __restrict__ b) {
    __shared__ float sIn[2][35][35];
    __shared__ float sW[32][50];
    __shared__ float sB[32];
    int tx = threadIdx.x, ty = threadIdx.y;
    int tid = ty * 16 + tx;
    for (int i = tid; i < 1600; i += 256) sW[i / 50][i % 50] = w[i];
    if (tid < 32) sB[tid] = b[tid];
    int y0 = blockIdx.y * 32 - 2, x0 = blockIdx.x * 32 - 2;
    for (int i = tid; i < 2 * 35 * 35; i += 256) {
        int ci = i / 1225; int rem = i - ci * 1225;
        int yy = rem / 35, xx = rem - yy * 35;
        int iy = y0 + yy, ix = x0 + xx;
        float v = 0.f;
        if (iy >= 0 && iy < 512 && ix >= 0 && ix < 512)
            v = x[(iy * 512 + ix) * 2 + ci];
        sIn[ci][yy][xx] = v;
    }
    __syncthreads();
    float r[50];
#pragma unroll
    for (int ci = 0; ci < 2; ci++)
#pragma unroll
        for (int ky = 0; ky < 5; ky++)
#pragma unroll
            for (int kx = 0; kx < 5; kx++)
                r[ci * 25 + ky * 5 + kx] = sIn[ci][ty * 2 + ky][tx * 2 + kx];
    int oy = blockIdx.y * 16 + ty, ox = blockIdx.x * 16 + tx;
    for (int co = 0; co < 32; co++) {
        float acc = sB[co];
#pragma unroll
        for (int k = 0; k < 50; k++) acc += r[k] * sW[co][k];
        g_h1[co * 65536 + oy * 256 + ox] = fmaxf(acc, 0.f);
    }
}

// ---------------- conv2: (32,256,256) -> (64,128,128), 5x5 s2 p2, +bias, relu ---
// block: 16x16 threads, each thread: 2x2 px * 8 out-channels. grid (4,4,8).
__global__ void conv2_kernel(const float* __restrict__ w,
                             const float* __restrict__ b) {
    __shared__ float sIn[67 * 68];
    __shared__ float sW[200];
    int tx = threadIdx.x, ty = threadIdx.y;
    int tid = ty * 16 + tx;
    int cog = blockIdx.z * 8;
    float acc[8][2][2];
#pragma unroll
    for (int co = 0; co < 8; co++) {
        float bb = b[cog + co];
        acc[co][0][0] = bb; acc[co][0][1] = bb;
        acc[co][1][0] = bb; acc[co][1][1] = bb;
    }
    int y0 = blockIdx.y * 64 - 2, x0 = blockIdx.x * 64 - 2;
    for (int ci = 0; ci < 32; ci++) {
        __syncthreads();
        const float* src = g_h1 + ci * 65536;
        for (int i = tid; i < 67 * 67; i += 256) {
            int yy = i / 67, xx = i - yy * 67;
            int iy = y0 + yy, ix = x0 + xx;
            float v = 0.f;
            if (iy >= 0 && iy < 256 && ix >= 0 && ix < 256) v = src[iy * 256 + ix];
            sIn[yy * 68 + xx] = v;
        }
        for (int i = tid; i < 200; i += 256) {
            int co = i / 25, k = i - co * 25;
            sW[i] = w[((cog + co) * 32 + ci) * 25 + k];
        }
        __syncthreads();
        float patch[7][7];
#pragma unroll
        for (int ly = 0; ly < 7; ly++)
#pragma unroll
            for (int lx = 0; lx < 7; lx++)
                patch[ly][lx] = sIn[(ty * 4 + ly) * 68 + tx * 4 + lx];
#pragma unroll
        for (int co = 0; co < 8; co++)
#pragma unroll
            for (int ky = 0; ky < 5; ky++)
#pragma unroll
                for (int kx = 0; kx < 5; kx++) {
                    float wv = sW[co * 25 + ky * 5 + kx];
                    acc[co][0][0] += patch[ky][kx] * wv;
                    acc[co][0][1] += patch[ky][kx + 2] * wv;
                    acc[co][1][0] += patch[ky + 2][kx] * wv;
                    acc[co][1][1] += patch[ky + 2][kx + 2] * wv;
                }
    }
    int oy0 = blockIdx.y * 32 + ty * 2, ox0 = blockIdx.x * 32 + tx * 2;
#pragma unroll
    for (int co = 0; co < 8; co++)
#pragma unroll
        for (int py = 0; py < 2; py++)
#pragma unroll
            for (int px = 0; px < 2; px++)
                g_h2[(cog + co) * 16384 + (oy0 + py) * 128 + (ox0 + px)] =
                    fmaxf(acc[co][py][px], 0.f);
}

// ---------------- global mean pool over 128x128 per channel ---------------------
__global__ void pool_kernel() {
    __shared__ float red[256];
    int c = blockIdx.x, tid = threadIdx.x;
    const float* src = g_h2 + c * 16384;
    float s = 0.f;
    for (int i = tid; i < 16384; i += 256) s += src[i];
    red[tid] = s;
    __syncthreads();
    for (int off = 128; off; off >>= 1) {
        if (tid < off) red[tid] += red[tid + off];
        __syncthreads();
    }
    if (tid == 0) g_feat[c] = red[0] * (1.f / 16384.f);
}

// ---------------- fc1 -> relu -> fc2, s = softplus(...), bitonic sort desc ------
__global__ void fc_sort_kernel(const float* __restrict__ fc1_w, const float* __restrict__ fc1_b,
                               const float* __restrict__ fc2_w, const float* __restrict__ fc2_b,
                               const float* __restrict__ s_w,  const float* __restrict__ s_b,
                               float* __restrict__ out) {
    __shared__ float sfeat[64];
    __shared__ float sf1[256];
    __shared__ float sf[256];
    __shared__ float ss[128];
    int tid = threadIdx.x;
    if (tid < 64) sfeat[tid] = g_feat[tid];
    __syncthreads();
    float acc = fc1_b[tid];
    for (int i = 0; i < 64; i++) acc += sfeat[i] * fc1_w[tid * 64 + i];
    sf1[tid] = fmaxf(acc, 0.f);
    __syncthreads();
    acc = fc2_b[tid];
    for (int i = 0; i < 256; i++) acc += sf1[i] * fc2_w[tid * 256 + i];
    sf[tid] = acc;
    g_f[tid] = acc;
    __syncthreads();
    if (tid < 128) {
        float a2 = s_b[tid];
        for (int i = 0; i < 256; i++) a2 += sf[i] * s_w[tid * 256 + i];
        ss[tid] = (a2 > 15.f) ? a2 : log1pf(expf(a2));
    }
    // bitonic ascending sort of 128 values
    for (int k = 2; k <= 128; k <<= 1)
        for (int j = k >> 1; j > 0; j >>= 1) {
            __syncthreads();
            if (tid < 128) {
                int ixj = tid ^ j;
                if (ixj > tid) {
                    float a = ss[tid], bv = ss[ixj];
                    bool up = ((tid & k) == 0);
                    if ((a > bv) == up) { ss[tid] = bv; ss[ixj] = a; }
                }
            }
        }
    __syncthreads();
    if (tid < 128) out[131072 + tid] = ss[127 - tid];   // descending
}

// ---------------- u/v generation: 262144-row GEMV, warp per row (HBM-bound) -----
__global__ void uvgen_kernel(const float* __restrict__ u_w, const float* __restrict__ u_b,
                             const float* __restrict__ v_w, const float* __restrict__ v_b) {
    __shared__ float sf[256];
    int tid = threadIdx.x;
    sf[tid] = g_f[tid];
    __syncthreads();
    int lane = tid & 31, warp = tid >> 5;
    int gw = blockIdx.x * 8 + warp;              // 0 .. 262143
    const float* W; const float* B; int r;
    if (gw < 131072) { W = u_w; B = u_b; r = gw; }
    else             { W = v_w; B = v_b; r = gw - 131072; }
    const float4* wr = (const float4*)(W + (size_t)r * 256);
    float acc = 0.f;
#pragma unroll
    for (int t = 0; t < 2; t++) {
        float4 w4 = wr[t * 32 + lane];
        int k = (t * 32 + lane) * 4;
        acc += w4.x * sf[k] + w4.y * sf[k + 1] + w4.z * sf[k + 2] + w4.w * sf[k + 3];
    }
#pragma unroll
    for (int off = 16; off; off >>= 1) acc += __shfl_xor_sync(0xffffffffu, acc, off);
    if (lane == 0) g_A[gw] = acc + B[r];
}

// ---------------- Gram: G = A^H A (128x128 complex), per matrix ------------------
__global__ void gram_kernel() {
    __shared__ float2 sA[32][16];
    __shared__ float2 sB2[32][16];
    int tx = threadIdx.x, ty = threadIdx.y;
    int tid = ty * 16 + tx;
    int mat = blockIdx.z;
    const float2* A = (const float2*)g_A + mat * 512 * 128;
    int k0 = blockIdx.y * 16, j0 = blockIdx.x * 16;
    float ax = 0.f, ay = 0.f;
    for (int i0 = 0; i0 < 512; i0 += 32) {
        __syncthreads();
        for (int l = tid; l < 512; l += 256) {
            int rr = l >> 4, cc = l & 15;
            sA[rr][cc]  = A[(i0 + rr) * 128 + k0 + cc];
            sB2[rr][cc] = A[(i0 + rr) * 128 + j0 + cc];
        }
        __syncthreads();
#pragma unroll
        for (int ii = 0; ii < 32; ii++) {
            float2 a = sA[ii][ty], bb = sB2[ii][tx];
            ax += a.x * bb.x + a.y * bb.y;       // conj(a)*b
            ay += a.x * bb.y - a.y * bb.x;
        }
    }
    g_G[mat * 16384 + (k0 + ty) * 128 + (j0 + tx)] = make_float2(ax, ay);
}

// ---------------- Cholesky (upper, Hermitian) with +1e-8 on each diagonal -------
__global__ void chol_kernel() {
    extern __shared__ float2 sG[];
    __shared__ float s_invd;
    int mat = blockIdx.x;
    int tid = threadIdx.x;
    int lane = tid & 31, warp = tid >> 5;
    for (int i = tid; i < 16384; i += 256) sG[i] = g_G[mat * 16384 + i];
    __syncthreads();
    for (int j = 0; j < 128; j++) {
        if (tid == 0) {
            float d = sqrtf(sG[j * 128 + j].x + 1e-8f);   // matches reference norm
            sG[j * 128 + j] = make_float2(d, 0.f);
            s_invd = 1.f / d;
        }
        __syncthreads();
        float invd = s_invd;
        for (int m = j + 1 + tid; m < 128; m += 256) {
            sG[j * 128 + m].x *= invd;
            sG[j * 128 + m].y *= invd;
        }
        __syncthreads();
        for (int k = j + 1 + warp; k < 128; k += 8) {
            float2 rjk = sG[j * 128 + k];
            for (int m = k + lane; m < 128; m += 32) {
                float2 rjm = sG[j * 128 + m];
                float2 gv = sG[k * 128 + m];
                gv.x -= rjk.x * rjm.x + rjk.y * rjm.y;   // G -= conj(rjk)*rjm
                gv.y -= rjk.x * rjm.y - rjk.y * rjm.x;
                sG[k * 128 + m] = gv;
            }
        }
        __syncthreads();
    }
    // write transposed R for conflict-free solve: RT[j][k]=R[k][j] (k<j), diag = 1/d
    for (int idx = tid; idx < 16384; idx += 256) {
        int j = idx >> 7, k = idx & 127;
        float2 v;
        if (k < j)       v = sG[k * 128 + j];
        else if (k == j) v = make_float2(1.f / sG[j * 128 + j].x, 0.f);
        else             v = make_float2(0.f, 0.f);
        g_RT[mat * 16384 + idx] = v;
    }
}

// ---------------- Q = A R^{-1}: per-row forward substitution, warp per row -------
__global__ void trisolve_kernel(float* __restrict__ out) {
    extern __shared__ float2 sRT[];
    int tid = threadIdx.x;
    int mat = blockIdx.x >> 6;
    int rowbase = (blockIdx.x & 63) * 8;
    for (int i = tid; i < 16384; i += 256) sRT[i] = g_RT[mat * 16384 + i];
    __syncthreads();
    int lane = tid & 31, warp = tid >> 5;
    int row = rowbase + warp;
    const float2* a = (const float2*)g_A + (mat * 512 + row) * 128;
    float2 av[4], xv[4];
#pragma unroll
    for (int t = 0; t < 4; t++) { av[t] = a[t * 32 + lane]; xv[t] = make_float2(0.f, 0.f); }
#pragma unroll
    for (int tj = 0; tj < 4; tj++) {
        for (int lj = 0; lj < 32; lj++) {
            int j = tj * 32 + lj;
            const float2* rrow = sRT + j * 128;
            float sx = 0.f, sy = 0.f;
#pragma unroll
            for (int t = 0; t < tj; t++) {
                float2 r = rrow[t * 32 + lane];
                sx += xv[t].x * r.x - xv[t].y * r.y;
                sy += xv[t].x * r.y + xv[t].y * r.x;
            }
            if (lane < lj) {
                float2 r = rrow[tj * 32 + lane];
                sx += xv[tj].x * r.x - xv[tj].y * r.y;
                sy += xv[tj].x * r.y + xv[tj].y * r.x;
            }
#pragma unroll
            for (int off = 16; off; off >>= 1) {
                sx += __shfl_xor_sync(0xffffffffu, sx, off);
                sy += __shfl_xor_sync(0xffffffffu, sy, off);
            }
            if (lane == lj) {
                float invd = rrow[j].x;                  // 1/r_jj
                xv[tj].x = (av[tj].x - sx) * invd;
                xv[tj].y = (av[tj].y - sy) * invd;
            }
        }
    }
    float2* dst = (mat == 0) ? (float2*)out : (float2*)(out + 131200);
#pragma unroll
    for (int t = 0; t < 4; t++) dst[row * 128 + t * 32 + lane] = xv[t];
}

// ---------------- launch ---------------------------------------------------------
extern "C" void kernel_launch(void* const* d_in, const int* in_sizes, int n_in,
                              void* d_out, int out_size) {
    const float* x   = (const float*)d_in[0];
    const float* c1w = (const float*)d_in[1];
    const float* c1b = (const float*)d_in[2];
    const float* c2w = (const float*)d_in[3];
    const float* c2b = (const float*)d_in[4];
    const float* f1w = (const float*)d_in[5];
    const float* f1b = (const float*)d_in[6];
    const float* f2w = (const float*)d_in[7];
    const float* f2b = (const float*)d_in[8];
    const float* sw  = (const float*)d_in[9];
    const float* sb  = (const float*)d_in[10];
    const float* uw  = (const float*)d_in[11];
    const float* ub  = (const float*)d_in[12];
    const float* vw  = (const float*)d_in[13];
    const float* vb  = (const float*)d_in[14];
    float* out = (float*)d_out;

    cudaFuncSetAttribute(chol_kernel,     cudaFuncAttributeMaxDynamicSharedMemorySize, 131072);
    cudaFuncSetAttribute(trisolve_kernel, cudaFuncAttributeMaxDynamicSharedMemorySize, 131072);

    conv1_kernel<<<dim3(16, 16), dim3(16, 16)>>>(x, c1w, c1b);
    conv2_kernel<<<dim3(4, 4, 8), dim3(16, 16)>>>(c2w, c2b);
    pool_kernel<<<64, 256>>>();
    fc_sort_kernel<<<1, 256>>>(f1w, f1b, f2w, f2b, sw, sb, out);
    uvgen_kernel<<<32768, 256>>>(uw, ub, vw, vb);
    gram_kernel<<<dim3(8, 8, 2), dim3(16, 16)>>>();
    chol_kernel<<<2, 256, 131072>>>();
    trisolve_kernel<<<128, 256, 131072>>>(out);
}

// round 3
// speedup vs baseline: 1.1318x; 1.1318x over previous
#include <cuda_runtime.h>
#include <math.h>

// ---------------- scratch (static device arrays; no allocations) ----------------
__device__ float  g_h1[32 * 256 * 256];      // conv1 output (8 MB)
__device__ float  g_pool[64 * 16];           // per-block pool partials
__device__ float  g_f[256];
__device__ float  g_A[2 * 512 * 128 * 2];    // pre-GS u then v, complex interleaved
__device__ float2 g_G[2 * 128 * 128];        // Gram matrices
__device__ float2 g_RT[2 * 128 * 128];       // RT[j][k] = R[k][j] (k<j), RT[j][j] = 1/r_jj

// ---------------- conv1: (2,512,512) -> (32,256,256), 5x5 s2 p2, +bias, relu ----
__global__ __launch_bounds__(256) void conv1_kernel(const float* __restrict__ x,
                             const float* __restrict__ w,
                             const float* __restrict__ b) {
    __shared__ float sIn[2][35][35];
    __shared__ float sW[32][50];
    __shared__ float sB[32];
    int tx = threadIdx.x, ty = threadIdx.y;
    int tid = ty * 16 + tx;
    for (int i = tid; i < 1600; i += 256) sW[i / 50][i % 50] = w[i];
    if (tid < 32) sB[tid] = b[tid];
    int y0 = blockIdx.y * 32 - 2, x0 = blockIdx.x * 32 - 2;
    for (int i = tid; i < 2 * 35 * 35; i += 256) {
        int ci = i / 1225; int rem = i - ci * 1225;
        int yy = rem / 35, xx = rem - yy * 35;
        int iy = y0 + yy, ix = x0 + xx;
        float v = 0.f;
        if (iy >= 0 && iy < 512 && ix >= 0 && ix < 512)
            v = x[(iy * 512 + ix) * 2 + ci];
        sIn[ci][yy][xx] = v;
    }
    __syncthreads();
    float r[50];
#pragma unroll
    for (int ci = 0; ci < 2; ci++)
#pragma unroll
        for (int ky = 0; ky < 5; ky++)
#pragma unroll
            for (int kx = 0; kx < 5; kx++)
                r[ci * 25 + ky * 5 + kx] = sIn[ci][ty * 2 + ky][tx * 2 + kx];
    int oy = blockIdx.y * 16 + ty, ox = blockIdx.x * 16 + tx;
    for (int co = 0; co < 32; co++) {
        float acc = sB[co];
#pragma unroll
        for (int k = 0; k < 50; k++) acc += r[k] * sW[co][k];
        g_h1[co * 65536 + oy * 256 + ox] = fmaxf(acc, 0.f);
    }
}

// ---------------- conv2 + fused mean-pool partials ------------------------------
// (32,256,256) -> (64,128,128) 5x5 s2 p2 +bias +relu, then per-channel block sum.
// block: 16x16 threads, each thread: 2x2 px * 8 out-channels. grid (4,4,8).
__global__ __launch_bounds__(256) void conv2_kernel(const float* __restrict__ w,
                             const float* __restrict__ b) {
    __shared__ float sIn[67 * 68];
    __shared__ float sW[200];
    __shared__ float sred[8 * 256];
    int tx = threadIdx.x, ty = threadIdx.y;
    int tid = ty * 16 + tx;
    int cog = blockIdx.z * 8;
    float acc[8][2][2];
#pragma unroll
    for (int co = 0; co < 8; co++) {
        float bb = b[cog + co];
        acc[co][0][0] = bb; acc[co][0][1] = bb;
        acc[co][1][0] = bb; acc[co][1][1] = bb;
    }
    int y0 = blockIdx.y * 64 - 2, x0 = blockIdx.x * 64 - 2;
    for (int ci = 0; ci < 32; ci++) {
        __syncthreads();
        const float* src = g_h1 + ci * 65536;
        for (int i = tid; i < 67 * 67; i += 256) {
            int yy = i / 67, xx = i - yy * 67;
            int iy = y0 + yy, ix = x0 + xx;
            float v = 0.f;
            if (iy >= 0 && iy < 256 && ix >= 0 && ix < 256) v = src[iy * 256 + ix];
            sIn[yy * 68 + xx] = v;
        }
        for (int i = tid; i < 200; i += 256) {
            int co = i / 25, k = i - co * 25;
            sW[i] = w[((cog + co) * 32 + ci) * 25 + k];
        }
        __syncthreads();
        float patch[7][7];
#pragma unroll
        for (int ly = 0; ly < 7; ly++)
#pragma unroll
            for (int lx = 0; lx < 7; lx++)
                patch[ly][lx] = sIn[(ty * 4 + ly) * 68 + tx * 4 + lx];
#pragma unroll
        for (int co = 0; co < 8; co++)
#pragma unroll
            for (int ky = 0; ky < 5; ky++)
#pragma unroll
                for (int kx = 0; kx < 5; kx++) {
                    float wv = sW[co * 25 + ky * 5 + kx];
                    acc[co][0][0] += patch[ky][kx] * wv;
                    acc[co][0][1] += patch[ky][kx + 2] * wv;
                    acc[co][1][0] += patch[ky + 2][kx] * wv;
                    acc[co][1][1] += patch[ky + 2][kx + 2] * wv;
                }
    }
    // relu + per-channel partial sum (pool), no global h2 traffic
    __syncthreads();
#pragma unroll
    for (int co = 0; co < 8; co++) {
        float s = fmaxf(acc[co][0][0], 0.f) + fmaxf(acc[co][0][1], 0.f)
                + fmaxf(acc[co][1][0], 0.f) + fmaxf(acc[co][1][1], 0.f);
        sred[co * 256 + tid] = s;
    }
    __syncthreads();
    int lane = tid & 31, warp = tid >> 5;   // 8 warps, warp w reduces channel w
    float s = 0.f;
#pragma unroll
    for (int i = 0; i < 8; i++) s += sred[warp * 256 + i * 32 + lane];
#pragma unroll
    for (int off = 16; off; off >>= 1) s += __shfl_xor_sync(0xffffffffu, s, off);
    if (lane == 0)
        g_pool[(cog + warp) * 16 + blockIdx.y * 4 + blockIdx.x] = s;
}

// ---------------- pool-finalize + fc1 + fc2 + s + softplus + sort ----------------
// 1024 threads, warp-per-row GEMVs with coalesced weight reads.
__global__ __launch_bounds__(1024) void fc_kernel(
                          const float* __restrict__ fc1_w, const float* __restrict__ fc1_b,
                          const float* __restrict__ fc2_w, const float* __restrict__ fc2_b,
                          const float* __restrict__ s_w,  const float* __restrict__ s_b,
                          float* __restrict__ out) {
    __shared__ float sfeat[64];
    __shared__ float sf1[256];
    __shared__ float sf[256];
    __shared__ float ss[128];
    int tid = threadIdx.x;
    int lane = tid & 31, warp = tid >> 5;      // 32 warps
    if (tid < 64) {
        float s = 0.f;
#pragma unroll
        for (int i = 0; i < 16; i++) s += g_pool[tid * 16 + i];
        sfeat[tid] = s * (1.f / 16384.f);
    }
    __syncthreads();
    // fc1: 256 rows of 64, relu
    for (int r = warp; r < 256; r += 32) {
        float2 w2 = ((const float2*)fc1_w)[r * 32 + lane];
        float a = w2.x * sfeat[2 * lane] + w2.y * sfeat[2 * lane + 1];
#pragma unroll
        for (int off = 16; off; off >>= 1) a += __shfl_xor_sync(0xffffffffu, a, off);
        if (lane == 0) sf1[r] = fmaxf(a + fc1_b[r], 0.f);
    }
    __syncthreads();
    // fc2: 256 rows of 256
    for (int r = warp; r < 256; r += 32) {
        const float4* wr = (const float4*)(fc2_w + r * 256);
        float a = 0.f;
#pragma unroll
        for (int t = 0; t < 2; t++) {
            float4 w4 = wr[t * 32 + lane];
            int k = (t * 32 + lane) * 4;
            a += w4.x * sf1[k] + w4.y * sf1[k + 1] + w4.z * sf1[k + 2] + w4.w * sf1[k + 3];
        }
#pragma unroll
        for (int off = 16; off; off >>= 1) a += __shfl_xor_sync(0xffffffffu, a, off);
        if (lane == 0) { float v = a + fc2_b[r]; sf[r] = v; g_f[r] = v; }
    }
    __syncthreads();
    // s head: 128 rows of 256, softplus
    for (int r = warp; r < 128; r += 32) {
        const float4* wr = (const float4*)(s_w + r * 256);
        float a = 0.f;
#pragma unroll
        for (int t = 0; t < 2; t++) {
            float4 w4 = wr[t * 32 + lane];
            int k = (t * 32 + lane) * 4;
            a += w4.x * sf[k] + w4.y * sf[k + 1] + w4.z * sf[k + 2] + w4.w * sf[k + 3];
        }
#pragma unroll
        for (int off = 16; off; off >>= 1) a += __shfl_xor_sync(0xffffffffu, a, off);
        if (lane == 0) {
            float v = a + s_b[r];
            ss[r] = (v > 15.f) ? v : log1pf(expf(v));
        }
    }
    // bitonic ascending sort of 128 values (all threads hit the syncs)
    for (int k = 2; k <= 128; k <<= 1)
        for (int j = k >> 1; j > 0; j >>= 1) {
            __syncthreads();
            if (tid < 128) {
                int ixj = tid ^ j;
                if (ixj > tid) {
                    float a = ss[tid], bv = ss[ixj];
                    bool up = ((tid & k) == 0);
                    if ((a > bv) == up) { ss[tid] = bv; ss[ixj] = a; }
                }
            }
        }
    __syncthreads();
    if (tid < 128) out[131072 + tid] = ss[127 - tid];   // descending
}

// ---------------- u/v generation: 262144-row GEMV, warp per row (HBM-bound) -----
__global__ __launch_bounds__(256) void uvgen_kernel(
                             const float* __restrict__ u_w, const float* __restrict__ u_b,
                             const float* __restrict__ v_w, const float* __restrict__ v_b) {
    __shared__ float sf[256];
    int tid = threadIdx.x;
    sf[tid] = g_f[tid];
    __syncthreads();
    int lane = tid & 31, warp = tid >> 5;
    int gw = blockIdx.x * 8 + warp;              // 0 .. 262143
    const float* W; const float* B; int r;
    if (gw < 131072) { W = u_w; B = u_b; r = gw; }
    else             { W = v_w; B = v_b; r = gw - 131072; }
    const float4* wr = (const float4*)(W + (size_t)r * 256);
    float acc = 0.f;
#pragma unroll
    for (int t = 0; t < 2; t++) {
        float4 w4 = wr[t * 32 + lane];
        int k = (t * 32 + lane) * 4;
        acc += w4.x * sf[k] + w4.y * sf[k + 1] + w4.z * sf[k + 2] + w4.w * sf[k + 3];
    }
#pragma unroll
    for (int off = 16; off; off >>= 1) acc += __shfl_xor_sync(0xffffffffu, acc, off);
    if (lane == 0) g_A[gw] = acc + B[r];
}

// ---------------- Gram: G = A^H A (128x128 complex), per matrix ------------------
__global__ __launch_bounds__(256) void gram_kernel() {
    __shared__ float2 sA[32][16];
    __shared__ float2 sB2[32][16];
    int tx = threadIdx.x, ty = threadIdx.y;
    int tid = ty * 16 + tx;
    int mat = blockIdx.z;
    const float2* A = (const float2*)g_A + mat * 512 * 128;
    int k0 = blockIdx.y * 16, j0 = blockIdx.x * 16;
    float ax = 0.f, ay = 0.f;
    for (int i0 = 0; i0 < 512; i0 += 32) {
        __syncthreads();
        for (int l = tid; l < 512; l += 256) {
            int rr = l >> 4, cc = l & 15;
            sA[rr][cc]  = A[(i0 + rr) * 128 + k0 + cc];
            sB2[rr][cc] = A[(i0 + rr) * 128 + j0 + cc];
        }
        __syncthreads();
#pragma unroll
        for (int ii = 0; ii < 32; ii++) {
            float2 a = sA[ii][ty], bb = sB2[ii][tx];
            ax += a.x * bb.x + a.y * bb.y;       // conj(a)*b
            ay += a.x * bb.y - a.y * bb.x;
        }
    }
    g_G[mat * 16384 + (k0 + ty) * 128 + (j0 + tx)] = make_float2(ax, ay);
}

// ---------------- Cholesky (upper, Hermitian), lazy scaling, 1 sync/iter --------
__global__ __launch_bounds__(256) void chol_kernel() {
    extern __shared__ float2 sG[];
    __shared__ float sInvArr[128];
    int mat = blockIdx.x;
    int tid = threadIdx.x;
    int lane = tid & 31, warp = tid >> 5;
    for (int i = tid; i < 16384; i += 256) sG[i] = g_G[mat * 16384 + i];
    __syncthreads();
    for (int j = 0; j < 128; j++) {
        float gjj = sG[j * 128 + j].x;                 // smem broadcast, all threads
        float d = sqrtf(gjj + 1e-8f);                  // matches reference norm
        float inv = 1.f / d;
        if (tid == 0) sInvArr[j] = inv;
        float inv2 = inv * inv;
        // trailing update with unscaled row j: G_km -= conj(g_jk) g_jm / d^2
        for (int k = j + 1 + warp; k < 128; k += 8) {
            float2 gjk = sG[j * 128 + k];
            float cx = gjk.x * inv2, cy = gjk.y * inv2;
            for (int m = k + lane; m < 128; m += 32) {
                float2 gjm = sG[j * 128 + m];
                float2 gv = sG[k * 128 + m];
                gv.x -= cx * gjm.x + cy * gjm.y;
                gv.y -= cx * gjm.y - cy * gjm.x;
                sG[k * 128 + m] = gv;
            }
        }
        __syncthreads();
    }
    // write transposed, scaled R: RT[j][k]=R[k][j]=g_kj/d_k (k<j), diag = 1/d_j
    for (int idx = tid; idx < 16384; idx += 256) {
        int j = idx >> 7, k = idx & 127;
        float2 v;
        if (k < j) {
            float2 g = sG[k * 128 + j];
            float iv = sInvArr[k];
            v = make_float2(g.x * iv, g.y * iv);
        } else if (k == j) {
            v = make_float2(sInvArr[j], 0.f);
        } else {
            v = make_float2(0.f, 0.f);
        }
        g_RT[mat * 16384 + idx] = v;
    }
}

// ---------------- Q = A R^{-1}: per-row forward substitution, warp per row -------
__global__ __launch_bounds__(256) void trisolve_kernel(float* __restrict__ out) {
    extern __shared__ float2 sRT[];
    int tid = threadIdx.x;
    int mat = blockIdx.x >> 6;
    int rowbase = (blockIdx.x & 63) * 8;
    for (int i = tid; i < 16384; i += 256) sRT[i] = g_RT[mat * 16384 + i];
    __syncthreads();
    int lane = tid & 31, warp = tid >> 5;
    int row = rowbase + warp;
    const float2* a = (const float2*)g_A + (mat * 512 + row) * 128;
    float2 av[4], xv[4];
#pragma unroll
    for (int t = 0; t < 4; t++) { av[t] = a[t * 32 + lane]; xv[t] = make_float2(0.f, 0.f); }
#pragma unroll
    for (int tj = 0; tj < 4; tj++) {
        for (int lj = 0; lj < 32; lj++) {
            int j = tj * 32 + lj;
            const float2* rrow = sRT + j * 128;
            float sx = 0.f, sy = 0.f;
#pragma unroll
            for (int t = 0; t < tj; t++) {
                float2 r = rrow[t * 32 + lane];
                sx += xv[t].x * r.x - xv[t].y * r.y;
                sy += xv[t].x * r.y + xv[t].y * r.x;
            }
            if (lane < lj) {
                float2 r = rrow[tj * 32 + lane];
                sx += xv[tj].x * r.x - xv[tj].y * r.y;
                sy += xv[tj].x * r.y + xv[tj].y * r.x;
            }
#pragma unroll
            for (int off = 16; off; off >>= 1) {
                sx += __shfl_xor_sync(0xffffffffu, sx, off);
                sy += __shfl_xor_sync(0xffffffffu, sy, off);
            }
            if (lane == lj) {
                float invd = rrow[j].x;                  // 1/r_jj
                xv[tj].x = (av[tj].x - sx) * invd;
                xv[tj].y = (av[tj].y - sy) * invd;
            }
        }
    }
    float2* dst = (mat == 0) ? (float2*)out : (float2*)(out + 131200);
#pragma unroll
    for (int t = 0; t < 4; t++) dst[row * 128 + t * 32 + lane] = xv[t];
}

// ---------------- launch ---------------------------------------------------------
extern "C" void kernel_launch(void* const* d_in, const int* in_sizes, int n_in,
                              void* d_out, int out_size) {
    const float* x   = (const float*)d_in[0];
    const float* c1w = (const float*)d_in[1];
    const float* c1b = (const float*)d_in[2];
    const float* c2w = (const float*)d_in[3];
    const float* c2b = (const float*)d_in[4];
    const float* f1w = (const float*)d_in[5];
    const float* f1b = (const float*)d_in[6];
    const float* f2w = (const float*)d_in[7];
    const float* f2b = (const float*)d_in[8];
    const float* sw  = (const float*)d_in[9];
    const float* sb  = (const float*)d_in[10];
    const float* uw  = (const float*)d_in[11];
    const float* ub  = (const float*)d_in[12];
    const float* vw  = (const float*)d_in[13];
    const float* vb  = (const float*)d_in[14];
    float* out = (float*)d_out;

    cudaFuncSetAttribute(chol_kernel,     cudaFuncAttributeMaxDynamicSharedMemorySize, 131072);
    cudaFuncSetAttribute(trisolve_kernel, cudaFuncAttributeMaxDynamicSharedMemorySize, 131072);

    conv1_kernel<<<dim3(16, 16), dim3(16, 16)>>>(x, c1w, c1b);
    conv2_kernel<<<dim3(4, 4, 8), dim3(16, 16)>>>(c2w, c2b);
    fc_kernel<<<1, 1024>>>(f1w, f1b, f2w, f2b, sw, sb, out);
    uvgen_kernel<<<32768, 256>>>(uw, ub, vw, vb);
    gram_kernel<<<dim3(8, 8, 2), dim3(16, 16)>>>();
    chol_kernel<<<2, 256, 131072>>>();
    trisolve_kernel<<<128, 256, 131072>>>(out);
}

// round 6
// speedup vs baseline: 1.2233x; 1.0808x over previous
#include <cuda_runtime.h>
#include <math.h>

// ---------------- f32x2 packed helpers (Blackwell, PTX ISA 8.6) -----------------
__device__ __forceinline__ unsigned long long pk2(float lo, float hi) {
    unsigned long long r;
    asm("mov.b64 %0, {%1, %2};" : "=l"(r) : "f"(lo), "f"(hi));
    return r;
}
__device__ __forceinline__ void upk2(float& lo, float& hi, unsigned long long v) {
    asm("mov.b64 {%0, %1}, %2;" : "=f"(lo), "=f"(hi) : "l"(v));
}
__device__ __forceinline__ void fma2(unsigned long long& d, unsigned long long a,
                                     unsigned long long b) {
    asm("fma.rn.f32x2 %0, %1, %2, %0;" : "+l"(d) : "l"(a), "l"(b));
}

// ---------------- scratch (static device arrays; no allocations) ----------------
__device__ float  g_h1[32 * 256 * 256];      // conv1 output (8 MB)
__device__ float  g_pool[64 * 16];           // per-block pool partials
__device__ float  g_f[256];
__device__ float  g_A[2 * 512 * 128 * 2];    // pre-GS u then v, complex interleaved
__device__ float2 g_G[2 * 128 * 128];        // Gram matrices
__device__ float2 g_RT[2 * 128 * 128];       // RT[j][k] = R[k][j] (k<j), RT[j][j] = 1/r_jj

// ---------------- conv1: (2,512,512) -> (32,256,256), 5x5 s2 p2, +bias, relu ----
// f32x2: accumulate channel pairs (2cop, 2cop+1) in one packed register.
__global__ __launch_bounds__(256) void conv1_kernel(const float* __restrict__ x,
                             const float* __restrict__ w,
                             const float* __restrict__ b) {
    __shared__ float sIn[2][35][35];
    __shared__ float2 sW2[16 * 50];          // {w[2cop][k], w[2cop+1][k]}
    __shared__ float sB[32];
    int tx = threadIdx.x, ty = threadIdx.y;
    int tid = ty * 16 + tx;
    for (int i = tid; i < 800; i += 256) {
        int cop = i / 50, k = i - cop * 50;
        sW2[i] = make_float2(w[(2 * cop) * 50 + k], w[(2 * cop + 1) * 50 + k]);
    }
    if (tid < 32) sB[tid] = b[tid];
    int y0 = blockIdx.y * 32 - 2, x0 = blockIdx.x * 32 - 2;
    for (int i = tid; i < 2 * 35 * 35; i += 256) {
        int ci = i / 1225; int rem = i - ci * 1225;
        int yy = rem / 35, xx = rem - yy * 35;
        int iy = y0 + yy, ix = x0 + xx;
        float v = 0.f;
        if (iy >= 0 && iy < 512 && ix >= 0 && ix < 512)
            v = x[(iy * 512 + ix) * 2 + ci];
        sIn[ci][yy][xx] = v;
    }
    __syncthreads();
    unsigned long long rp[50];
#pragma unroll
    for (int ci = 0; ci < 2; ci++)
#pragma unroll
        for (int ky = 0; ky < 5; ky++)
#pragma unroll
            for (int kx = 0; kx < 5; kx++) {
                float v = sIn[ci][ty * 2 + ky][tx * 2 + kx];
                rp[ci * 25 + ky * 5 + kx] = pk2(v, v);
            }
    int oy = blockIdx.y * 16 + ty, ox = blockIdx.x * 16 + tx;
    const unsigned long long* sw2u = (const unsigned long long*)sW2;
#pragma unroll 4
    for (int cop = 0; cop < 16; cop++) {
        unsigned long long acc = pk2(sB[2 * cop], sB[2 * cop + 1]);
#pragma unroll
        for (int k = 0; k < 50; k++) fma2(acc, rp[k], sw2u[cop * 50 + k]);
        float a0, a1; upk2(a0, a1, acc);
        g_h1[(2 * cop) * 65536 + oy * 256 + ox]     = fmaxf(a0, 0.f);
        g_h1[(2 * cop + 1) * 65536 + oy * 256 + ox] = fmaxf(a1, 0.f);
    }
}

// ---------------- conv2 + fused mean-pool partials ------------------------------
// (32,256,256) -> (64,128,128) 5x5 s2 p2 +bias +relu, per-channel block sum.
// f32x2: pack the 2 px outputs; weights splatted into smem float2.
__global__ __launch_bounds__(256) void conv2_kernel(const float* __restrict__ w,
                             const float* __restrict__ b) {
    __shared__ float sIn[67 * 68];
    __shared__ float2 sW2[200];              // splatted {wv, wv}
    __shared__ float sred[8 * 256];
    int tx = threadIdx.x, ty = threadIdx.y;
    int tid = ty * 16 + tx;
    int cog = blockIdx.z * 8;
    unsigned long long acc2[8][2];           // [co][py] = {px0, px1}
#pragma unroll
    for (int co = 0; co < 8; co++) {
        float bb = b[cog + co];
        acc2[co][0] = pk2(bb, bb);
        acc2[co][1] = pk2(bb, bb);
    }
    int y0 = blockIdx.y * 64 - 2, x0 = blockIdx.x * 64 - 2;
    const unsigned long long* sw2u = (const unsigned long long*)sW2;
    for (int ci = 0; ci < 32; ci++) {
        __syncthreads();
        const float* src = g_h1 + ci * 65536;
        for (int i = tid; i < 67 * 67; i += 256) {
            int yy = i / 67, xx = i - yy * 67;
            int iy = y0 + yy, ix = x0 + xx;
            float v = 0.f;
            if (iy >= 0 && iy < 256 && ix >= 0 && ix < 256) v = src[iy * 256 + ix];
            sIn[yy * 68 + xx] = v;
        }
        for (int i = tid; i < 200; i += 256) {
            int co = i / 25, k = i - co * 25;
            float wv = w[((cog + co) * 32 + ci) * 25 + k];
            sW2[i] = make_float2(wv, wv);
        }
        __syncthreads();
        // packed patch pairs: pp[ly][kx] = {in[ly][kx], in[ly][kx+2]}
        unsigned long long pp[7][5];
#pragma unroll
        for (int ly = 0; ly < 7; ly++) {
            float pr[7];
#pragma unroll
            for (int lx = 0; lx < 7; lx++)
                pr[lx] = sIn[(ty * 4 + ly) * 68 + tx * 4 + lx];
#pragma unroll
            for (int kx = 0; kx < 5; kx++)
                pp[ly][kx] = pk2(pr[kx], pr[kx + 2]);
        }
#pragma unroll
        for (int co = 0; co < 8; co++)
#pragma unroll
            for (int ky = 0; ky < 5; ky++)
#pragma unroll
                for (int kx = 0; kx < 5; kx++) {
                    unsigned long long wv2 = sw2u[co * 25 + ky * 5 + kx];
                    fma2(acc2[co][0], pp[ky][kx],     wv2);
                    fma2(acc2[co][1], pp[ky + 2][kx], wv2);
                }
    }
    // relu + per-channel partial sum (pool), no global h2 traffic
    __syncthreads();
#pragma unroll
    for (int co = 0; co < 8; co++) {
        float a00, a01, a10, a11;
        upk2(a00, a01, acc2[co][0]);
        upk2(a10, a11, acc2[co][1]);
        sred[co * 256 + tid] = fmaxf(a00, 0.f) + fmaxf(a01, 0.f)
                             + fmaxf(a10, 0.f) + fmaxf(a11, 0.f);
    }
    __syncthreads();
    int lane = tid & 31, warp = tid >> 5;   // 8 warps, warp w reduces channel w
    float s = 0.f;
#pragma unroll
    for (int i = 0; i < 8; i++) s += sred[warp * 256 + i * 32 + lane];
#pragma unroll
    for (int off = 16; off; off >>= 1) s += __shfl_xor_sync(0xffffffffu, s, off);
    if (lane == 0)
        g_pool[(cog + warp) * 16 + blockIdx.y * 4 + blockIdx.x] = s;
}

// ---------------- pool-finalize + fc1 + fc2 + s + softplus + sort ----------------
__global__ __launch_bounds__(1024) void fc_kernel(
                          const float* __restrict__ fc1_w, const float* __restrict__ fc1_b,
                          const float* __restrict__ fc2_w, const float* __restrict__ fc2_b,
                          const float* __restrict__ s_w,  const float* __restrict__ s_b,
                          float* __restrict__ out) {
    __shared__ float sfeat[64];
    __shared__ float sf1[256];
    __shared__ float sf[256];
    __shared__ float ss[128];
    int tid = threadIdx.x;
    int lane = tid & 31, warp = tid >> 5;      // 32 warps
    if (tid < 64) {
        float s = 0.f;
#pragma unroll
        for (int i = 0; i < 16; i++) s += g_pool[tid * 16 + i];
        sfeat[tid] = s * (1.f / 16384.f);
    }
    __syncthreads();
    for (int r = warp; r < 256; r += 32) {
        float2 w2 = ((const float2*)fc1_w)[r * 32 + lane];
        float a = w2.x * sfeat[2 * lane] + w2.y * sfeat[2 * lane + 1];
#pragma unroll
        for (int off = 16; off; off >>= 1) a += __shfl_xor_sync(0xffffffffu, a, off);
        if (lane == 0) sf1[r] = fmaxf(a + fc1_b[r], 0.f);
    }
    __syncthreads();
    for (int r = warp; r < 256; r += 32) {
        const float4* wr = (const float4*)(fc2_w + r * 256);
        float a = 0.f;
#pragma unroll
        for (int t = 0; t < 2; t++) {
            float4 w4 = wr[t * 32 + lane];
            int k = (t * 32 + lane) * 4;
            a += w4.x * sf1[k] + w4.y * sf1[k + 1] + w4.z * sf1[k + 2] + w4.w * sf1[k + 3];
        }
#pragma unroll
        for (int off = 16; off; off >>= 1) a += __shfl_xor_sync(0xffffffffu, a, off);
        if (lane == 0) { float v = a + fc2_b[r]; sf[r] = v; g_f[r] = v; }
    }
    __syncthreads();
    for (int r = warp; r < 128; r += 32) {
        const float4* wr = (const float4*)(s_w + r * 256);
        float a = 0.f;
#pragma unroll
        for (int t = 0; t < 2; t++) {
            float4 w4 = wr[t * 32 + lane];
            int k = (t * 32 + lane) * 4;
            a += w4.x * sf[k] + w4.y * sf[k + 1] + w4.z * sf[k + 2] + w4.w * sf[k + 3];
        }
#pragma unroll
        for (int off = 16; off; off >>= 1) a += __shfl_xor_sync(0xffffffffu, a, off);
        if (lane == 0) {
            float v = a + s_b[r];
            ss[r] = (v > 15.f) ? v : log1pf(expf(v));
        }
    }
    for (int k = 2; k <= 128; k <<= 1)
        for (int j = k >> 1; j > 0; j >>= 1) {
            __syncthreads();
            if (tid < 128) {
                int ixj = tid ^ j;
                if (ixj > tid) {
                    float a = ss[tid], bv = ss[ixj];
                    bool up = ((tid & k) == 0);
                    if ((a > bv) == up) { ss[tid] = bv; ss[ixj] = a; }
                }
            }
        }
    __syncthreads();
    if (tid < 128) out[131072 + tid] = ss[127 - tid];   // descending
}

// ---------------- u/v generation: warp handles 2 rows (MLP=4, HBM-bound) --------
__global__ __launch_bounds__(256) void uvgen_kernel(
                             const float* __restrict__ u_w, const float* __restrict__ u_b,
                             const float* __restrict__ v_w, const float* __restrict__ v_b) {
    __shared__ float sf[256];
    int tid = threadIdx.x;
    sf[tid] = g_f[tid];
    __syncthreads();
    int lane = tid & 31, warp = tid >> 5;
    int gw = (blockIdx.x * 8 + warp) * 2;        // first of 2 rows, 0..262142
    const float* W; const float* B; int r;
    if (gw < 131072) { W = u_w; B = u_b; r = gw; }
    else             { W = v_w; B = v_b; r = gw - 131072; }
    const float4* wr0 = (const float4*)(W + (size_t)r * 256);
    const float4* wr1 = wr0 + 64;
    // issue all 4 loads before any dependent math
    float4 a0 = wr0[lane], a1 = wr0[32 + lane];
    float4 b0 = wr1[lane], b1 = wr1[32 + lane];
    int k0 = lane * 4, k1 = (32 + lane) * 4;
    float accA = a0.x * sf[k0] + a0.y * sf[k0 + 1] + a0.z * sf[k0 + 2] + a0.w * sf[k0 + 3]
               + a1.x * sf[k1] + a1.y * sf[k1 + 1] + a1.z * sf[k1 + 2] + a1.w * sf[k1 + 3];
    float accB = b0.x * sf[k0] + b0.y * sf[k0 + 1] + b0.z * sf[k0 + 2] + b0.w * sf[k0 + 3]
               + b1.x * sf[k1] + b1.y * sf[k1 + 1] + b1.z * sf[k1 + 2] + b1.w * sf[k1 + 3];
#pragma unroll
    for (int off = 16; off; off >>= 1) {
        accA += __shfl_xor_sync(0xffffffffu, accA, off);
        accB += __shfl_xor_sync(0xffffffffu, accB, off);
    }
    if (lane == 0) {
        g_A[gw]     = accA + B[r];
        g_A[gw + 1] = accB + B[r + 1];
    }
}

// ---------------- Gram: G = A^H A (128x128 complex), per matrix ------------------
__global__ __launch_bounds__(256) void gram_kernel() {
    __shared__ float2 sA[32][16];
    __shared__ float2 sB2[32][16];
    int tx = threadIdx.x, ty = threadIdx.y;
    int tid = ty * 16 + tx;
    int mat = blockIdx.z;
    const float2* A = (const float2*)g_A + mat * 512 * 128;
    int k0 = blockIdx.y * 16, j0 = blockIdx.x * 16;
    float ax = 0.f, ay = 0.f;
    for (int i0 = 0; i0 < 512; i0 += 32) {
        __syncthreads();
        for (int l = tid; l < 512; l += 256) {
            int rr = l >> 4, cc = l & 15;
            sA[rr][cc]  = A[(i0 + rr) * 128 + k0 + cc];
            sB2[rr][cc] = A[(i0 + rr) * 128 + j0 + cc];
        }
        __syncthreads();
#pragma unroll
        for (int ii = 0; ii < 32; ii++) {
            float2 a = sA[ii][ty], bb = sB2[ii][tx];
            ax += a.x * bb.x + a.y * bb.y;       // conj(a)*b
            ay += a.x * bb.y - a.y * bb.x;
        }
    }
    g_G[mat * 16384 + (k0 + ty) * 128 + (j0 + tx)] = make_float2(ax, ay);
}

// ---------------- Cholesky (upper, Hermitian), lazy scaling, 1 sync/iter --------
__global__ __launch_bounds__(512) void chol_kernel() {
    extern __shared__ float2 sG[];
    __shared__ float sInvArr[128];
    int mat = blockIdx.x;
    int tid = threadIdx.x;
    int lane = tid & 31, warp = tid >> 5;     // 16 warps
    for (int i = tid; i < 16384; i += 512) sG[i] = g_G[mat * 16384 + i];
    __syncthreads();
    for (int j = 0; j < 128; j++) {
        float gjj = sG[j * 128 + j].x;                 // smem broadcast
        float d = sqrtf(gjj + 1e-8f);                  // matches reference norm
        float inv = 1.f / d;
        if (tid == 0) sInvArr[j] = inv;
        float inv2 = inv * inv;
        for (int k = j + 1 + warp; k < 128; k += 16) {
            float2 gjk = sG[j * 128 + k];
            float cx = gjk.x * inv2, cy = gjk.y * inv2;
            for (int m = k + lane; m < 128; m += 32) {
                float2 gjm = sG[j * 128 + m];
                float2 gv = sG[k * 128 + m];
                gv.x -= cx * gjm.x + cy * gjm.y;
                gv.y -= cx * gjm.y - cy * gjm.x;
                sG[k * 128 + m] = gv;
            }
        }
        __syncthreads();
    }
    for (int idx = tid; idx < 16384; idx += 512) {
        int j = idx >> 7, k = idx & 127;
        float2 v;
        if (k < j) {
            float2 g = sG[k * 128 + j];
            float iv = sInvArr[k];
            v = make_float2(g.x * iv, g.y * iv);
        } else if (k == j) {
            v = make_float2(sInvArr[j], 0.f);
        } else {
            v = make_float2(0.f, 0.f);
        }
        g_RT[mat * 16384 + idx] = v;
    }
}

// ---------------- Q = A R^{-1}: per-row forward substitution, warp per row -------
__global__ __launch_bounds__(256) void trisolve_kernel(float* __restrict__ out) {
    extern __shared__ float2 sRT[];
    int tid = threadIdx.x;
    int mat = blockIdx.x >> 6;
    int rowbase = (blockIdx.x & 63) * 8;
    for (int i = tid; i < 16384; i += 256) sRT[i] = g_RT[mat * 16384 + i];
    __syncthreads();
    int lane = tid & 31, warp = tid >> 5;
    int row = rowbase + warp;
    const float2* a = (const float2*)g_A + (mat * 512 + row) * 128;
    float2 av[4], xv[4];
#pragma unroll
    for (int t = 0; t < 4; t++) { av[t] = a[t * 32 + lane]; xv[t] = make_float2(0.f, 0.f); }
#pragma unroll
    for (int tj = 0; tj < 4; tj++) {
        for (int lj = 0; lj < 32; lj++) {
            int j = tj * 32 + lj;
            const float2* rrow = sRT + j * 128;
            float sx = 0.f, sy = 0.f;
#pragma unroll
            for (int t = 0; t < tj; t++) {
                float2 r = rrow[t * 32 + lane];
                sx += xv[t].x * r.x - xv[t].y * r.y;
                sy += xv[t].x * r.y + xv[t].y * r.x;
            }
            if (lane < lj) {
                float2 r = rrow[tj * 32 + lane];
                sx += xv[tj].x * r.x - xv[tj].y * r.y;
                sy += xv[tj].x * r.y + xv[tj].y * r.x;
            }
#pragma unroll
            for (int off = 16; off; off >>= 1) {
                sx += __shfl_xor_sync(0xffffffffu, sx, off);
                sy += __shfl_xor_sync(0xffffffffu, sy, off);
            }
            if (lane == lj) {
                float invd = rrow[j].x;                  // 1/r_jj
                xv[tj].x = (av[tj].x - sx) * invd;
                xv[tj].y = (av[tj].y - sy) * invd;
            }
        }
    }
    float2* dst = (mat == 0) ? (float2*)out : (float2*)(out + 131200);
#pragma unroll
    for (int t = 0; t < 4; t++) dst[row * 128 + t * 32 + lane] = xv[t];
}

// ---------------- launch ---------------------------------------------------------
extern "C" void kernel_launch(void* const* d_in, const int* in_sizes, int n_in,
                              void* d_out, int out_size) {
    const float* x   = (const float*)d_in[0];
    const float* c1w = (const float*)d_in[1];
    const float* c1b = (const float*)d_in[2];
    const float* c2w = (const float*)d_in[3];
    const float* c2b = (const float*)d_in[4];
    const float* f1w = (const float*)d_in[5];
    const float* f1b = (const float*)d_in[6];
    const float* f2w = (const float*)d_in[7];
    const float* f2b = (const float*)d_in[8];
    const float* sw  = (const float*)d_in[9];
    const float* sb  = (const float*)d_in[10];
    const float* uw  = (const float*)d_in[11];
    const float* ub  = (const float*)d_in[12];
    const float* vw  = (const float*)d_in[13];
    const float* vb  = (const float*)d_in[14];
    float* out = (float*)d_out;

    cudaFuncSetAttribute(chol_kernel,     cudaFuncAttributeMaxDynamicSharedMemorySize, 131072);
    cudaFuncSetAttribute(trisolve_kernel, cudaFuncAttributeMaxDynamicSharedMemorySize, 131072);

    conv1_kernel<<<dim3(16, 16), dim3(16, 16)>>>(x, c1w, c1b);
    conv2_kernel<<<dim3(4, 4, 8), dim3(16, 16)>>>(c2w, c2b);
    fc_kernel<<<1, 1024>>>(f1w, f1b, f2w, f2b, sw, sb, out);
    uvgen_kernel<<<16384, 256>>>(uw, ub, vw, vb);
    gram_kernel<<<dim3(8, 8, 2), dim3(16, 16)>>>();
    chol_kernel<<<2, 512, 131072>>>();
    trisolve_kernel<<<128, 256, 131072>>>(out);
}